// round 6
// baseline (speedup 1.0000x reference)
#include <cuda_runtime.h>

// out[b, s, d] = in[b, s, d] + PE[s, d]
// PE[s, 2i]   = sin(s / 10000^(2i/1024)),  PE[s, 2i+1] = cos(...)
//
// B=8, S=4096, D=1024, fp32 — 268 MB per launch. DRAM-bound at ~73% of
// spec (mixed R/W stream). R6: 256-bit LDG/STG (sm_10x .v8.f32) — halves
// memory-instruction count, 1KB-contiguous warp requests, drops the inert
// L2-policy asm from R4/R5. Each thread owns one float8 of one PE row
// (4 sin/cos pairs computed once, reused across the 8 batches).

#define SEQ_LEN 4096
#define D_MODEL 1024
#define BATCH   8
#define THREADS 128   // 128 threads * 8 floats = 1024 floats = one PE row

struct f8 { float a,b,c,d,e,f,g,h; };

__device__ __forceinline__ f8 ldg256(const float* p) {
    f8 v;
    asm volatile("ld.global.nc.v8.f32 {%0,%1,%2,%3,%4,%5,%6,%7}, [%8];"
                 : "=f"(v.a), "=f"(v.b), "=f"(v.c), "=f"(v.d),
                   "=f"(v.e), "=f"(v.f), "=f"(v.g), "=f"(v.h)
                 : "l"(p));
    return v;
}

__device__ __forceinline__ void stg256(float* p, const f8& v) {
    asm volatile("st.global.v8.f32 [%0], {%1,%2,%3,%4,%5,%6,%7,%8};"
                 :: "l"(p),
                    "f"(v.a), "f"(v.b), "f"(v.c), "f"(v.d),
                    "f"(v.e), "f"(v.f), "f"(v.g), "f"(v.h)
                 : "memory");
}

__global__ void __launch_bounds__(THREADS, 16)
pe_add_kernel(const float* __restrict__ in, float* __restrict__ out) {
    const int pos = blockIdx.x;        // sequence position 0..4095
    const int t   = threadIdx.x;       // float8 index within row 0..127

    // PE for this thread's 8 dims (8t..8t+7) = pairs 4t..4t+3.
    const float LOG2_10000 = 13.287712379549449f;
    const float fpos = (float)pos;

    f8 pe;
    {
        float s, c;
        float ang;
        ang = fpos / exp2f(((float)(8 * t)     * (1.0f / 1024.0f)) * LOG2_10000);
        sincosf(ang, &s, &c); pe.a = s; pe.b = c;
        ang = fpos / exp2f(((float)(8 * t + 2) * (1.0f / 1024.0f)) * LOG2_10000);
        sincosf(ang, &s, &c); pe.c = s; pe.d = c;
        ang = fpos / exp2f(((float)(8 * t + 4) * (1.0f / 1024.0f)) * LOG2_10000);
        sincosf(ang, &s, &c); pe.e = s; pe.f = c;
        ang = fpos / exp2f(((float)(8 * t + 6) * (1.0f / 1024.0f)) * LOG2_10000);
        sincosf(ang, &s, &c); pe.g = s; pe.h = c;
    }

    // 32-bit element offsets in floats.
    const int batch_stride = SEQ_LEN * D_MODEL;      // 4,194,304 floats
    int idx = pos * D_MODEL + t * 8;

    // 2-deep pipeline over the 8 batches.
    f8 cur = ldg256(in + idx);
#pragma unroll
    for (int b = 0; b < BATCH; ++b) {
        int next_idx = idx + batch_stride;
        f8 nxt;
        if (b < BATCH - 1) nxt = ldg256(in + next_idx);
        f8 v = cur;
        v.a += pe.a; v.b += pe.b; v.c += pe.c; v.d += pe.d;
        v.e += pe.e; v.f += pe.f; v.g += pe.g; v.h += pe.h;
        stg256(out + idx, v);
        cur = nxt;
        idx = next_idx;
    }
}

extern "C" void kernel_launch(void* const* d_in, const int* in_sizes, int n_in,
                              void* d_out, int out_size) {
    const float* in  = (const float*)d_in[0];
    float*       out = (float*)d_out;
    pe_add_kernel<<<SEQ_LEN, THREADS>>>(in, out);
}